// round 3
// baseline (speedup 1.0000x reference)
#include <cuda_runtime.h>
#include <cuda_bf16.h>
#include <cstdint>
#include <math.h>

#define T_STEPS 2048
#define BATCH   64
#define EDIM    256
#define HDIM    256
#define G4      1024
#define VOCAB   50257
#define TBsz    (T_STEPS*BATCH)

// ---------------- device scratch (no cudaMalloc allowed) ----------------
__device__ float d_P[(size_t)VOCAB * G4];   // projected embedding table, permuted cols
__device__ float d_Whh2[G4 * HDIM];         // row-permuted W_hh
__device__ float d_bias2[G4];               // permuted (b_ih + b_hh)

// permutation: j = g*256 + k, k = r*32+u  ->  pj = r*128 + g*32 + u
__device__ __forceinline__ int permj(int j) {
    int g = j >> 8; int k = j & 255; int r = k >> 5; int u = k & 31;
    return r * 128 + g * 32 + u;
}

// ---------------- kernel 0: reorder W_hh rows + bias ----------------
__global__ void reorder_kernel(const float* __restrict__ Whh,
                               const float* __restrict__ bih,
                               const float* __restrict__ bhh) {
    int j = blockIdx.x;
    int pj = permj(j);
    d_Whh2[pj * 256 + threadIdx.x] = Whh[j * 256 + threadIdx.x];
    if (threadIdx.x == 0) d_bias2[pj] = bih[j] + bhh[j];
}

// ---------------- kernel 1: P = emb @ W_ih^T (NT gemm), permuted cols ----------------
#define BM 128
#define BN 128
#define BK 32
__global__ void __launch_bounds__(256)
proj_kernel(const float* __restrict__ emb, const float* __restrict__ Wih) {
    __shared__ float As[BK][BM + 1];
    __shared__ float Bs[BK][BN + 1];
    int l  = threadIdx.x;
    int v0 = blockIdx.x * BM;
    int j0 = blockIdx.y * BN;
    int ty = l >> 4, tx = l & 15;

    float acc[8][8];
#pragma unroll
    for (int i = 0; i < 8; i++)
#pragma unroll
        for (int j = 0; j < 8; j++) acc[i][j] = 0.f;

    for (int kt = 0; kt < EDIM; kt += BK) {
        for (int idx = l; idx < BM * BK; idx += 256) {
            int vr = idx >> 5; int e = idx & 31;
            int v = v0 + vr;
            As[e][vr] = (v < VOCAB) ? emb[v * EDIM + kt + e] : 0.f;
        }
        for (int idx = l; idx < BN * BK; idx += 256) {
            int jr = idx >> 5; int e = idx & 31;
            Bs[e][jr] = Wih[(j0 + jr) * EDIM + kt + e];
        }
        __syncthreads();
#pragma unroll
        for (int kk = 0; kk < BK; kk++) {
            float a[8], b[8];
#pragma unroll
            for (int i = 0; i < 8; i++) a[i] = As[kk][ty * 8 + i];
#pragma unroll
            for (int i = 0; i < 8; i++) b[i] = Bs[kk][tx * 8 + i];
#pragma unroll
            for (int i = 0; i < 8; i++)
#pragma unroll
                for (int j = 0; j < 8; j++) acc[i][j] = fmaf(a[i], b[j], acc[i][j]);
        }
        __syncthreads();
    }
    int jb  = j0 + tx * 8;
    int pj0 = permj(jb);            // 8 consecutive j stay consecutive after perm
#pragma unroll
    for (int i = 0; i < 8; i++) {
        int v = v0 + ty * 8 + i;
        if (v < VOCAB) {
#pragma unroll
            for (int jj = 0; jj < 8; jj++)
                d_P[(size_t)v * G4 + pj0 + jj] = acc[i][jj];
        }
    }
}

// ---------------- kernel 2: persistent cluster LSTM ----------------
__device__ __forceinline__ void cluster_sync_() {
    asm volatile("barrier.cluster.arrive.aligned;" ::: "memory");
    asm volatile("barrier.cluster.wait.aligned;" ::: "memory");
}
__device__ __forceinline__ void st_cluster_f32(uint32_t addr, uint32_t rank, float v) {
    uint32_t ra;
    asm volatile("mapa.shared::cluster.u32 %0, %1, %2;" : "=r"(ra) : "r"(addr), "r"(rank));
    asm volatile("st.shared::cluster.f32 [%0], %1;" :: "r"(ra), "f"(v) : "memory");
}
__device__ __forceinline__ float sigm(float x) { return 1.f / (1.f + expf(-x)); }

// smem float layout
#define SM_WT   0        // 32768  : Wt[e*128+row], transposed slice of Whh2
#define SM_HB   32768    // 2048   : 2 parities x 256 units x 4 cols
#define SM_PART 34816    // 512
#define SM_GV   35328    // 512
#define SM_WZ   35840    // 256
#define SM_FLOATS 36096
#define LSTM_SMEM_BYTES (SM_FLOATS * 4)

__global__ void __launch_bounds__(256, 1) __cluster_dims__(8, 1, 1)
lstm_kernel(const int* __restrict__ sentences, const float* __restrict__ noise,
            const float* __restrict__ W_z, const float* __restrict__ b_z_p,
            float* __restrict__ out) {
    extern __shared__ float sm[];
    float* sm_Wt   = sm + SM_WT;
    float* sm_hbuf = sm + SM_HB;
    float* sm_part = sm + SM_PART;
    float* sm_gv   = sm + SM_GV;
    float* sm_Wz   = sm + SM_WZ;

    int tid = threadIdx.x;
    uint32_t r;
    asm("mov.u32 %0, %%cluster_ctarank;" : "=r"(r));
    int cid   = blockIdx.x >> 3;
    int colg0 = cid * 4;

    // load Wt (transposed) for this CTA's 128 gate rows
    for (int idx = tid; idx < 128 * 256; idx += 256) {
        int rr = idx >> 8; int e = idx & 255;
        sm_Wt[e * 128 + rr] = d_Whh2[(r * 128 + rr) * 256 + e];
    }
    sm_Wz[tid] = (tid < 256) ? W_z[tid] : 0.f;
    for (int idx = tid; idx < 2048; idx += 256) sm_hbuf[idx] = 0.f;
    float breg = (tid < 128) ? d_bias2[r * 128 + tid] : 0.f;
    float creg = 0.f;
    float bz   = b_z_p[0];
    __syncthreads();
    cluster_sync_();

    uint32_t hb32 = (uint32_t)__cvta_generic_to_shared(sm_hbuf);
    int row = tid & 127;
    int kh  = tid >> 7;

    for (int t = 0; t < T_STEPS; t++) {
        int par = t & 1;

        // prefetch this step's x-gate contributions (hidden behind matmul)
        float xg0 = 0.f, xg1 = 0.f, xg2 = 0.f, xg3 = 0.f;
        if (tid < 128) {
            int base = t * BATCH + colg0;
            int t0 = sentences[base + 0];
            int t1 = sentences[base + 1];
            int t2 = sentences[base + 2];
            int t3 = sentences[base + 3];
            int ro = (int)r * 128 + row;
            xg0 = d_P[(size_t)t0 * G4 + ro];
            xg1 = d_P[(size_t)t1 * G4 + ro];
            xg2 = d_P[(size_t)t2 * G4 + ro];
            xg3 = d_P[(size_t)t3 * G4 + ro];
        }

        // CTA0 computes pz/z for step t-1 from hbuf[par] (holds h_{t-1})
        if (r == 0 && t > 0 && tid < 128) {
            int col = tid >> 5, lane = tid & 31;
            float acc = 0.f;
#pragma unroll
            for (int jj = 0; jj < 8; jj++) {
                int k = lane + jj * 32;
                acc += sm_hbuf[par * 1024 + k * 4 + col] * sm_Wz[k];
            }
#pragma unroll
            for (int off = 16; off; off >>= 1)
                acc += __shfl_down_sync(0xffffffffu, acc, off);
            if (lane == 0) {
                float pz = sigm(acc + bz);
                int o = (t - 1) * BATCH + colg0 + col;
                out[o]        = pz;
                out[TBsz + o] = (noise[o] < pz) ? 1.f : 0.f;
            }
        }

        // recurrent matmul: each thread does (row, 4 cols) over half of K
        float a0 = 0.f, a1 = 0.f, a2 = 0.f, a3 = 0.f;
        {
            const float4* hb = (const float4*)(sm_hbuf + par * 1024);
            int e0 = kh << 7;
#pragma unroll 8
            for (int e = e0; e < e0 + 128; e++) {
                float  w  = sm_Wt[e * 128 + row];
                float4 h4 = hb[e];
                a0 = fmaf(w, h4.x, a0);
                a1 = fmaf(w, h4.y, a1);
                a2 = fmaf(w, h4.z, a2);
                a3 = fmaf(w, h4.w, a3);
            }
        }
        if (kh) {
            sm_part[row * 4 + 0] = a0; sm_part[row * 4 + 1] = a1;
            sm_part[row * 4 + 2] = a2; sm_part[row * 4 + 3] = a3;
        }
        __syncthreads();
        if (tid < 128) {
            float g0 = a0 + sm_part[row * 4 + 0] + xg0 + breg;
            float g1 = a1 + sm_part[row * 4 + 1] + xg1 + breg;
            float g2 = a2 + sm_part[row * 4 + 2] + xg2 + breg;
            float g3 = a3 + sm_part[row * 4 + 3] + xg3 + breg;
            sm_gv[row * 4 + 0] = g0; sm_gv[row * 4 + 1] = g1;
            sm_gv[row * 4 + 2] = g2; sm_gv[row * 4 + 3] = g3;
        }
        __syncthreads();
        if (tid < 128) {
            int u = tid & 31, col = tid >> 5;
            float gi = sm_gv[(u)      * 4 + col];
            float gf = sm_gv[(32 + u) * 4 + col];
            float gg = sm_gv[(64 + u) * 4 + col];
            float go = sm_gv[(96 + u) * 4 + col];
            creg = sigm(gf) * creg + sigm(gi) * tanhf(gg);
            float h = sigm(go) * tanhf(creg);
            int k = (int)r * 32 + u;
            uint32_t off = hb32 + (uint32_t)(((par ^ 1) * 1024 + k * 4 + col) * 4);
#pragma unroll
            for (int p = 0; p < 8; p++) st_cluster_f32(off, (uint32_t)p, h);
        }
        cluster_sync_();
    }

    // final pz for t = 2047 (h_2047 is in parity 0)
    if (r == 0 && tid < 128) {
        int col = tid >> 5, lane = tid & 31;
        float acc = 0.f;
#pragma unroll
        for (int jj = 0; jj < 8; jj++) {
            int k = lane + jj * 32;
            acc += sm_hbuf[0 * 1024 + k * 4 + col] * sm_Wz[k];
        }
#pragma unroll
        for (int off = 16; off; off >>= 1)
            acc += __shfl_down_sync(0xffffffffu, acc, off);
        if (lane == 0) {
            float pz = sigm(acc + bz);
            int o = 2047 * BATCH + colg0 + col;
            out[o]        = pz;
            out[TBsz + o] = (noise[o] < pz) ? 1.f : 0.f;
        }
    }
}

// ---------------- kernel 3: per-column stable stream compaction ----------------
__global__ void __launch_bounds__(256)
compact_kernel(const int* __restrict__ sentences, float* __restrict__ out) {
    int b = blockIdx.x;
    int tid = threadIdx.x;
    __shared__ int wsum[8];
    __shared__ int s_total;

    int t0 = tid * 8;
    float zv[8];
    int pre[8];
    int cnt = 0;
#pragma unroll
    for (int i = 0; i < 8; i++) {
        zv[i]  = out[TBsz + (t0 + i) * BATCH + b];
        pre[i] = cnt;
        cnt += (zv[i] > 0.5f) ? 1 : 0;
    }
    int lane = tid & 31, w = tid >> 5;
    int x = cnt;
#pragma unroll
    for (int off = 1; off < 32; off <<= 1) {
        int y = __shfl_up_sync(0xffffffffu, x, off);
        if (lane >= off) x += y;
    }
    if (lane == 31) wsum[w] = x;
    __syncthreads();
    if (tid == 0) {
        int s = 0;
        for (int k = 0; k < 8; k++) { int v = wsum[k]; wsum[k] = s; s += v; }
        s_total = s;
    }
    __syncthreads();
    int base = wsum[w] + (x - cnt);
#pragma unroll
    for (int i = 0; i < 8; i++) {
        if (zv[i] > 0.5f) {
            int pos = base + pre[i];
            out[2 * TBsz + pos * BATCH + b] = (float)sentences[(t0 + i) * BATCH + b];
        }
    }
    int total = s_total;
    for (int p = total + tid; p < T_STEPS; p += 256)
        out[2 * TBsz + p * BATCH + b] = 0.0f;   // PAD_ID = 0
    if (tid == 0) out[3 * TBsz + b] = (float)total;
}

// ---------------- launch ----------------
extern "C" void kernel_launch(void* const* d_in, const int* in_sizes, int n_in,
                              void* d_out, int out_size) {
    const int*   sentences = (const int*)  d_in[0];
    const float* noise     = (const float*)d_in[1];
    const float* emb       = (const float*)d_in[2];
    const float* W_ih      = (const float*)d_in[3];
    const float* W_hh      = (const float*)d_in[4];
    const float* b_ih      = (const float*)d_in[5];
    const float* b_hh      = (const float*)d_in[6];
    const float* W_z       = (const float*)d_in[7];
    const float* b_z       = (const float*)d_in[8];
    float* out = (float*)d_out;

    cudaFuncSetAttribute(lstm_kernel, cudaFuncAttributeMaxDynamicSharedMemorySize,
                         LSTM_SMEM_BYTES);

    reorder_kernel<<<G4, 256>>>(W_hh, b_ih, b_hh);
    proj_kernel<<<dim3((VOCAB + BM - 1) / BM, G4 / BN), 256>>>(emb, W_ih);
    lstm_kernel<<<128, 256, LSTM_SMEM_BYTES>>>(sentences, noise, W_z, b_z, out);
    compact_kernel<<<BATCH, 256>>>(sentences, out);
}

// round 4
// speedup vs baseline: 1.0823x; 1.0823x over previous
#include <cuda_runtime.h>
#include <cuda_bf16.h>
#include <cstdint>
#include <math.h>

#define T_STEPS 2048
#define BATCH   64
#define EDIM    256
#define HDIM    256
#define G4      1024
#define VOCAB   50257
#define TBsz    (T_STEPS*BATCH)

typedef unsigned long long ull;

// ---------------- device scratch (no cudaMalloc allowed) ----------------
__device__ float d_P[(size_t)VOCAB * G4];   // projected embedding table, permuted cols
__device__ float d_Whh2[G4 * HDIM];         // row-permuted W_hh
__device__ float d_bias2[G4];               // permuted (b_ih + b_hh)

// permutation: j = g*256 + k, k = r*32+u  ->  pj = r*128 + g*32 + u
__device__ __forceinline__ int permj(int j) {
    int g = j >> 8; int k = j & 255; int r = k >> 5; int u = k & 31;
    return r * 128 + g * 32 + u;
}

// ---------------- kernel 0: reorder W_hh rows + bias ----------------
__global__ void reorder_kernel(const float* __restrict__ Whh,
                               const float* __restrict__ bih,
                               const float* __restrict__ bhh) {
    int j = blockIdx.x;
    int pj = permj(j);
    d_Whh2[pj * 256 + threadIdx.x] = Whh[j * 256 + threadIdx.x];
    if (threadIdx.x == 0) d_bias2[pj] = bih[j] + bhh[j];
}

// ---------------- kernel 1: P = emb @ W_ih^T (NT gemm), permuted cols ----------------
#define BM 128
#define BN 128
#define BK 32
__global__ void __launch_bounds__(256)
proj_kernel(const float* __restrict__ emb, const float* __restrict__ Wih) {
    __shared__ float As[BK][BM + 1];
    __shared__ float Bs[BK][BN + 1];
    int l  = threadIdx.x;
    int v0 = blockIdx.x * BM;
    int j0 = blockIdx.y * BN;
    int ty = l >> 4, tx = l & 15;

    float acc[8][8];
#pragma unroll
    for (int i = 0; i < 8; i++)
#pragma unroll
        for (int j = 0; j < 8; j++) acc[i][j] = 0.f;

    for (int kt = 0; kt < EDIM; kt += BK) {
        for (int idx = l; idx < BM * BK; idx += 256) {
            int vr = idx >> 5; int e = idx & 31;
            int v = v0 + vr;
            As[e][vr] = (v < VOCAB) ? emb[v * EDIM + kt + e] : 0.f;
        }
        for (int idx = l; idx < BN * BK; idx += 256) {
            int jr = idx >> 5; int e = idx & 31;
            Bs[e][jr] = Wih[(j0 + jr) * EDIM + kt + e];
        }
        __syncthreads();
#pragma unroll
        for (int kk = 0; kk < BK; kk++) {
            float a[8], b[8];
#pragma unroll
            for (int i = 0; i < 8; i++) a[i] = As[kk][ty * 8 + i];
#pragma unroll
            for (int i = 0; i < 8; i++) b[i] = Bs[kk][tx * 8 + i];
#pragma unroll
            for (int i = 0; i < 8; i++)
#pragma unroll
                for (int j = 0; j < 8; j++) acc[i][j] = fmaf(a[i], b[j], acc[i][j]);
        }
        __syncthreads();
    }
    int jb  = j0 + tx * 8;
    int pj0 = permj(jb);            // 8 consecutive j stay consecutive after perm
#pragma unroll
    for (int i = 0; i < 8; i++) {
        int v = v0 + ty * 8 + i;
        if (v < VOCAB) {
#pragma unroll
            for (int jj = 0; jj < 8; jj++)
                d_P[(size_t)v * G4 + pj0 + jj] = acc[i][jj];
        }
    }
}

// ---------------- kernel 2: persistent cluster LSTM ----------------
__device__ __forceinline__ void cluster_sync_() {
    asm volatile("barrier.cluster.arrive.aligned;" ::: "memory");
    asm volatile("barrier.cluster.wait.aligned;" ::: "memory");
}
__device__ __forceinline__ ull pack2(float a, float b) {
    ull r; asm("mov.b64 %0, {%1, %2};" : "=l"(r) : "f"(a), "f"(b)); return r;
}
__device__ __forceinline__ void fma2(ull& d, ull a, ull b) {
    asm("fma.rn.f32x2 %0, %1, %2, %0;" : "+l"(d) : "l"(a), "l"(b));
}
union F2 { ull u; float2 f; };

__device__ __forceinline__ float sigf(float x) {
    return __fdividef(1.f, 1.f + __expf(-x));
}
__device__ __forceinline__ float tanhfast(float x) {
    return 1.f - 2.f * __fdividef(1.f, __expf(2.f * x) + 1.f);
}

// smem float layout
#define SM_W4   0        // 32768 : w4[(e*32+u)*4+g]
#define SM_HB   32768    // 2048  : 2 par x 4 col x 256 k  (col-major per col)
#define SM_PART 34816    // 512   : (col*32+u)*4
#define SM_WZ   35328    // 256
#define SM_FLOATS 35584
#define LSTM_SMEM_BYTES (SM_FLOATS * 4)

__global__ void __launch_bounds__(256, 1) __cluster_dims__(8, 1, 1)
lstm_kernel(const int* __restrict__ sentences, const float* __restrict__ noise,
            const float* __restrict__ W_z, const float* __restrict__ b_z_p,
            float* __restrict__ out) {
    extern __shared__ float sm[];
    float* sm_W4   = sm + SM_W4;
    float* sm_hbuf = sm + SM_HB;
    float* sm_part = sm + SM_PART;
    float* sm_Wz   = sm + SM_WZ;

    int tid = threadIdx.x;
    uint32_t r;
    asm("mov.u32 %0, %%cluster_ctarank;" : "=r"(r));
    int cid   = blockIdx.x >> 3;
    int colg0 = cid * 4;
    int u   = tid & 31;
    int col = (tid >> 5) & 3;
    int kh  = tid >> 7;

    // load W4: sm_W4[(e*32+u)*4+g] = Whh2[(r*128+g*32+u)*256 + e]
    for (int idx = tid; idx < 32768; idx += 256) {
        int e = idx >> 7, rem = idx & 127, uu = rem >> 2, g = rem & 3;
        sm_W4[idx] = d_Whh2[((int)r * 128 + g * 32 + uu) * 256 + e];
    }
    sm_Wz[tid] = W_z[tid & 255];
    for (int idx = tid; idx < 2048; idx += 256) sm_hbuf[idx] = 0.f;

    float b0 = 0.f, b1 = 0.f, b2 = 0.f, b3 = 0.f, creg = 0.f;
    if (kh == 0) {
        b0 = d_bias2[r * 128 + u];
        b1 = d_bias2[r * 128 + 32 + u];
        b2 = d_bias2[r * 128 + 64 + u];
        b3 = d_bias2[r * 128 + 96 + u];
    }
    float bz = b_z_p[0];
    __syncthreads();

    // precompute peer SMEM base addresses for hbuf
    uint32_t hb_local = (uint32_t)__cvta_generic_to_shared(sm_hbuf);
    uint32_t peer[8];
#pragma unroll
    for (int p = 0; p < 8; p++)
        asm("mapa.shared::cluster.u32 %0, %1, %2;" : "=r"(peer[p]) : "r"(hb_local), "r"(p));

    int   tok = sentences[colg0 + col];   // token for t=0, this thread's column
    float nz  = 0.f;                      // noise for output (t-1), loaded in-flight
    cluster_sync_();

    for (int t = 0; t < T_STEPS; t++) {
        int par = t & 1;

        // x-gate loads for THIS step (token was prefetched last step; hidden by matmul)
        float xg0 = 0.f, xg1 = 0.f, xg2 = 0.f, xg3 = 0.f;
        if (kh == 0) {
            const float* Pp = d_P + (size_t)tok * G4 + (int)r * 128 + u;
            xg0 = Pp[0]; xg1 = Pp[32]; xg2 = Pp[64]; xg3 = Pp[96];
        }

        // pz/z for output t-1: CTA r handles column r (r<4), warp 0 only
        if ((int)r < 4 && tid < 32 && t > 0) {
            float acc = 0.f;
            const float* hrow = sm_hbuf + par * 1024 + (int)r * 256;
#pragma unroll
            for (int jj = 0; jj < 8; jj++)
                acc += hrow[tid + jj * 32] * sm_Wz[tid + jj * 32];
#pragma unroll
            for (int off = 16; off; off >>= 1)
                acc += __shfl_down_sync(0xffffffffu, acc, off);
            if (tid == 0) {
                float pz = sigf(acc + bz);
                int o = (t - 1) * BATCH + colg0 + (int)r;
                out[o]        = pz;
                out[TBsz + o] = (nz < pz) ? 1.f : 0.f;
            }
        }

        // recurrent matmul: thread = (unit u, col, K-half), 4 gates packed f32x2
        ull a01 = 0ull, a23 = 0ull;
        {
            const float4* hb4 = (const float4*)(sm_hbuf + par * 1024 + col * 256 + kh * 128);
            const float4* wp  = (const float4*)sm_W4 + kh * 128 * 32 + u;
#pragma unroll 8
            for (int eb = 0; eb < 32; eb++) {
                float4 h4 = hb4[eb];
                float hv[4] = {h4.x, h4.y, h4.z, h4.w};
#pragma unroll
                for (int j = 0; j < 4; j++) {
                    float4 w = wp[(eb * 4 + j) * 32];
                    ull hh = pack2(hv[j], hv[j]);
                    fma2(a01, pack2(w.x, w.y), hh);
                    fma2(a23, pack2(w.z, w.w), hh);
                }
            }
        }

        if (kh) {
            F2 x, y; x.u = a01; y.u = a23;
            ((float4*)sm_part)[col * 32 + u] = make_float4(x.f.x, x.f.y, y.f.x, y.f.y);
        }
        __syncthreads();

        if (kh == 0) {
            float4 p = ((float4*)sm_part)[col * 32 + u];
            F2 x, y; x.u = a01; y.u = a23;
            float gi = x.f.x + p.x + xg0 + b0;
            float gf = x.f.y + p.y + xg1 + b1;
            float gg = y.f.x + p.z + xg2 + b2;
            float go = y.f.y + p.w + xg3 + b3;
            creg = sigf(gf) * creg + sigf(gi) * tanhfast(gg);
            float h = sigf(go) * tanhfast(creg);
            uint32_t off = (uint32_t)((((par ^ 1) * 1024) + col * 256 + (int)r * 32 + u) * 4);
#pragma unroll
            for (int p8 = 0; p8 < 8; p8++)
                asm volatile("st.shared::cluster.f32 [%0], %1;"
                             :: "r"(peer[p8] + off), "f"(h) : "memory");
        }

        asm volatile("barrier.cluster.arrive.aligned;" ::: "memory");
        // prefetch next token + this step's noise while the barrier drains
        {
            int tn = (t + 1 < T_STEPS) ? t + 1 : T_STEPS - 1;
            tok = sentences[tn * BATCH + colg0 + col];
            if ((int)r < 4 && tid < 32)
                nz = noise[t * BATCH + colg0 + (int)r];
        }
        asm volatile("barrier.cluster.wait.aligned;" ::: "memory");
    }

    // final pz for t_out = 2047 (h_2047 is in parity 0)
    if ((int)r < 4 && tid < 32) {
        float acc = 0.f;
        const float* hrow = sm_hbuf + (int)r * 256;   // parity 0
#pragma unroll
        for (int jj = 0; jj < 8; jj++)
            acc += hrow[tid + jj * 32] * sm_Wz[tid + jj * 32];
#pragma unroll
        for (int off = 16; off; off >>= 1)
            acc += __shfl_down_sync(0xffffffffu, acc, off);
        if (tid == 0) {
            float pz = sigf(acc + bz);
            int o = 2047 * BATCH + colg0 + (int)r;
            out[o]        = pz;
            out[TBsz + o] = (nz < pz) ? 1.f : 0.f;
        }
    }
}

// ---------------- kernel 3: per-column stable stream compaction ----------------
__global__ void __launch_bounds__(256)
compact_kernel(const int* __restrict__ sentences, float* __restrict__ out) {
    int b = blockIdx.x;
    int tid = threadIdx.x;
    __shared__ int wsum[8];
    __shared__ int s_total;

    int t0 = tid * 8;
    float zv[8];
    int pre[8];
    int cnt = 0;
#pragma unroll
    for (int i = 0; i < 8; i++) {
        zv[i]  = out[TBsz + (t0 + i) * BATCH + b];
        pre[i] = cnt;
        cnt += (zv[i] > 0.5f) ? 1 : 0;
    }
    int lane = tid & 31, w = tid >> 5;
    int x = cnt;
#pragma unroll
    for (int off = 1; off < 32; off <<= 1) {
        int y = __shfl_up_sync(0xffffffffu, x, off);
        if (lane >= off) x += y;
    }
    if (lane == 31) wsum[w] = x;
    __syncthreads();
    if (tid == 0) {
        int s = 0;
        for (int k = 0; k < 8; k++) { int v = wsum[k]; wsum[k] = s; s += v; }
        s_total = s;
    }
    __syncthreads();
    int base = wsum[w] + (x - cnt);
#pragma unroll
    for (int i = 0; i < 8; i++) {
        if (zv[i] > 0.5f) {
            int pos = base + pre[i];
            out[2 * TBsz + pos * BATCH + b] = (float)sentences[(t0 + i) * BATCH + b];
        }
    }
    int total = s_total;
    for (int p = total + tid; p < T_STEPS; p += 256)
        out[2 * TBsz + p * BATCH + b] = 0.0f;   // PAD_ID = 0
    if (tid == 0) out[3 * TBsz + b] = (float)total;
}

// ---------------- launch ----------------
extern "C" void kernel_launch(void* const* d_in, const int* in_sizes, int n_in,
                              void* d_out, int out_size) {
    const int*   sentences = (const int*)  d_in[0];
    const float* noise     = (const float*)d_in[1];
    const float* emb       = (const float*)d_in[2];
    const float* W_ih      = (const float*)d_in[3];
    const float* W_hh      = (const float*)d_in[4];
    const float* b_ih      = (const float*)d_in[5];
    const float* b_hh      = (const float*)d_in[6];
    const float* W_z       = (const float*)d_in[7];
    const float* b_z       = (const float*)d_in[8];
    float* out = (float*)d_out;

    cudaFuncSetAttribute(lstm_kernel, cudaFuncAttributeMaxDynamicSharedMemorySize,
                         LSTM_SMEM_BYTES);

    reorder_kernel<<<G4, 256>>>(W_hh, b_ih, b_hh);
    proj_kernel<<<dim3((VOCAB + BM - 1) / BM, G4 / BN), 256>>>(emb, W_ih);
    lstm_kernel<<<128, 256, LSTM_SMEM_BYTES>>>(sentences, noise, W_z, b_z, out);
    compact_kernel<<<BATCH, 256>>>(sentences, out);
}

// round 5
// speedup vs baseline: 1.9396x; 1.7921x over previous
#include <cuda_runtime.h>
#include <cuda_bf16.h>
#include <cstdint>
#include <math.h>

#define T_STEPS 2048
#define BATCH   64
#define EDIM    256
#define HDIM    256
#define G4      1024
#define VOCAB   50257
#define TBsz    (T_STEPS*BATCH)

typedef unsigned long long ull;

// ---------------- device scratch (no cudaMalloc allowed) ----------------
__device__ float d_P[(size_t)VOCAB * G4];   // projected embedding table, permuted cols
__device__ float d_Whh2[G4 * HDIM];         // row-permuted W_hh
__device__ float d_bias2[G4];               // permuted (b_ih + b_hh)

// permutation: j = g*256 + k, k = r*32+u  ->  pj = r*128 + g*32 + u
__device__ __forceinline__ int permj(int j) {
    int g = j >> 8; int k = j & 255; int r = k >> 5; int u = k & 31;
    return r * 128 + g * 32 + u;
}

__device__ __forceinline__ ull pack2(float a, float b) {
    ull r; asm("mov.b64 %0, {%1, %2};" : "=l"(r) : "f"(a), "f"(b)); return r;
}
__device__ __forceinline__ void fma2(ull& d, ull a, ull b) {
    asm("fma.rn.f32x2 %0, %1, %2, %0;" : "+l"(d) : "l"(a), "l"(b));
}
union F2 { ull u; float2 f; };

// ---------------- kernel 0: reorder W_hh rows + bias ----------------
__global__ void reorder_kernel(const float* __restrict__ Whh,
                               const float* __restrict__ bih,
                               const float* __restrict__ bhh) {
    int j = blockIdx.x;
    int pj = permj(j);
    d_Whh2[pj * 256 + threadIdx.x] = Whh[j * 256 + threadIdx.x];
    if (threadIdx.x == 0) d_bias2[pj] = bih[j] + bhh[j];
}

// ---------------- kernel 1: P = emb @ W_ih^T (NT gemm), permuted cols, f32x2 ----------------
#define BM 128
#define BN 128
#define BK 32
__global__ void __launch_bounds__(256)
proj_kernel(const float* __restrict__ emb, const float* __restrict__ Wih) {
    __shared__ float As[BK][BM + 1];
    __shared__ float Bs[BK][BN + 1];
    int l  = threadIdx.x;
    int v0 = blockIdx.x * BM;
    int j0 = blockIdx.y * BN;
    int ty = l >> 4, tx = l & 15;

    ull acc2[8][4];
#pragma unroll
    for (int i = 0; i < 8; i++)
#pragma unroll
        for (int j = 0; j < 4; j++) acc2[i][j] = 0ull;

    for (int kt = 0; kt < EDIM; kt += BK) {
        for (int idx = l; idx < BM * BK; idx += 256) {
            int vr = idx >> 5; int e = idx & 31;
            int v = v0 + vr;
            As[e][vr] = (v < VOCAB) ? emb[v * EDIM + kt + e] : 0.f;
        }
        for (int idx = l; idx < BN * BK; idx += 256) {
            int jr = idx >> 5; int e = idx & 31;
            Bs[e][jr] = Wih[(j0 + jr) * EDIM + kt + e];
        }
        __syncthreads();
#pragma unroll
        for (int kk = 0; kk < BK; kk++) {
            float a[8], b[8];
#pragma unroll
            for (int i = 0; i < 8; i++) a[i] = As[kk][ty * 8 + i];
#pragma unroll
            for (int i = 0; i < 8; i++) b[i] = Bs[kk][tx * 8 + i];
            ull pa[8], pb[4];
#pragma unroll
            for (int i = 0; i < 8; i++) pa[i] = pack2(a[i], a[i]);
#pragma unroll
            for (int j = 0; j < 4; j++) pb[j] = pack2(b[2 * j], b[2 * j + 1]);
#pragma unroll
            for (int i = 0; i < 8; i++)
#pragma unroll
                for (int j = 0; j < 4; j++) fma2(acc2[i][j], pa[i], pb[j]);
        }
        __syncthreads();
    }
    int jb  = j0 + tx * 8;
    int pj0 = permj(jb);            // 8 consecutive j stay consecutive after perm
#pragma unroll
    for (int i = 0; i < 8; i++) {
        int v = v0 + ty * 8 + i;
        if (v < VOCAB) {
#pragma unroll
            for (int j = 0; j < 4; j++) {
                F2 x; x.u = acc2[i][j];
                d_P[(size_t)v * G4 + pj0 + 2 * j]     = x.f.x;
                d_P[(size_t)v * G4 + pj0 + 2 * j + 1] = x.f.y;
            }
        }
    }
}

// ---------------- kernel 2: persistent cluster LSTM ----------------
__device__ __forceinline__ void cluster_sync_() {
    asm volatile("barrier.cluster.arrive.aligned;" ::: "memory");
    asm volatile("barrier.cluster.wait.aligned;" ::: "memory");
}
__device__ __forceinline__ float sigf(float x) {
    return __fdividef(1.f, 1.f + __expf(-x));
}
__device__ __forceinline__ float tanhfast(float x) {
    return 1.f - 2.f * __fdividef(1.f, __expf(2.f * x) + 1.f);
}

// smem float layout (weights live in registers now)
#define SM_HB   0        // 2048 : 2 par x 4 col x 256 k
#define SM_PART 2048     // 1024 : 2 kh x 128 row x 4 col (float4 per row)
#define SM_WZ   3072     // 256
#define SM_TOK  3328     // 8 ints (2 par x 4 col)
#define SM_FLOATS 3336
#define LSTM_SMEM_BYTES (SM_FLOATS * 4)

__global__ void __launch_bounds__(256, 1) __cluster_dims__(8, 1, 1)
lstm_kernel(const int* __restrict__ sentences, const float* __restrict__ noise,
            const float* __restrict__ W_z, const float* __restrict__ b_z_p,
            float* __restrict__ out) {
    extern __shared__ float sm[];
    float* sm_hbuf = sm + SM_HB;
    float* sm_part = sm + SM_PART;
    float* sm_Wz   = sm + SM_WZ;
    int*   sm_tok  = (int*)(sm + SM_TOK);

    int tid = threadIdx.x;
    uint32_t r;
    asm("mov.u32 %0, %%cluster_ctarank;" : "=r"(r));
    int cid   = blockIdx.x >> 3;
    int colg0 = cid * 4;
    int row = tid & 127;          // gate-row within CTA slice (g*32+u)
    int kh  = tid >> 7;           // K-half
    int u   = tid & 31;
    int col = (tid >> 5) & 3;

    // register-resident weights: this thread's gate-row, its K-half, packed in pairs
    ull wp[64];
    {
        const float2* wsrc = (const float2*)(d_Whh2 + ((int)r * 128 + row) * 256 + kh * 128);
#pragma unroll
        for (int i = 0; i < 64; i++) {
            float2 w = wsrc[i];
            wp[i] = pack2(w.x, w.y);
        }
    }

    sm_Wz[tid] = W_z[tid & 255];
    for (int idx = tid; idx < 2048; idx += 256) sm_hbuf[idx] = 0.f;
    if (tid < 4) sm_tok[tid] = sentences[colg0 + tid];   // tokens for t=0 -> buf 0

    // epilogue constants (pointwise threads: tid<128 -> unit u, col)
    float b0 = 0.f, b1 = 0.f, b2 = 0.f, b3 = 0.f, creg = 0.f;
    if (tid < 128) {
        b0 = d_bias2[r * 128 + u];
        b1 = d_bias2[r * 128 + 32 + u];
        b2 = d_bias2[r * 128 + 64 + u];
        b3 = d_bias2[r * 128 + 96 + u];
    }
    float bz = b_z_p[0];
    __syncthreads();

    // peer SMEM base addresses for hbuf
    uint32_t hb_local = (uint32_t)__cvta_generic_to_shared(sm_hbuf);
    uint32_t peer[8];
#pragma unroll
    for (int p = 0; p < 8; p++)
        asm("mapa.shared::cluster.u32 %0, %1, %2;" : "=r"(peer[p]) : "r"(hb_local), "r"(p));

    float nz = 0.f;              // noise for output step t-1 (lane holding pz store)
    cluster_sync_();

    for (int t = 0; t < T_STEPS; t++) {
        int par = t & 1;

        // ---- x-gate loads for this step (pointwise threads), overlap matmul ----
        float xg0 = 0.f, xg1 = 0.f, xg2 = 0.f, xg3 = 0.f;
        if (tid < 128) {
            int tok = sm_tok[par * 4 + col];
            const float* Pp = d_P + (size_t)tok * G4 + (int)r * 128 + u;
            xg0 = Pp[0]; xg1 = Pp[32]; xg2 = Pp[64]; xg3 = Pp[96];
        }

        // ---- next-step token prefetch (4 threads of kh=1 last warp) ----
        int nxt_tok = 0;
        if (tid >= 252) {
            int tn = (t + 1 < T_STEPS) ? t + 1 : T_STEPS - 1;
            nxt_tok = sentences[tn * BATCH + colg0 + (tid - 252)];
        }

        // ---- pz/z for output t-1: CTA r handles column r (r<4), warp 4 (kh=1) ----
        if ((int)r < 4 && (tid >> 5) == 4 && t > 0) {
            int lane = tid & 31;
            float acc = 0.f;
            const float* hrow = sm_hbuf + par * 1024 + (int)r * 256;
#pragma unroll
            for (int jj = 0; jj < 8; jj++)
                acc += hrow[lane + jj * 32] * sm_Wz[lane + jj * 32];
#pragma unroll
            for (int off = 16; off; off >>= 1)
                acc += __shfl_down_sync(0xffffffffu, acc, off);
            if (lane == 0) {
                float pz = sigf(acc + bz);
                int o = (t - 1) * BATCH + colg0 + (int)r;
                out[o]        = pz;
                out[TBsz + o] = (nz < pz) ? 1.f : 0.f;
            }
        }

        // ---- recurrent matmul: row x 4 cols over K-half, weights in registers ----
        // h loads are warp-wide broadcasts (all lanes same address).
        ull aA0 = 0ull, aB0 = 0ull, aA1 = 0ull, aB1 = 0ull;
        ull aA2 = 0ull, aB2 = 0ull, aA3 = 0ull, aB3 = 0ull;
        {
            const ulonglong2* hp0 = (const ulonglong2*)(sm_hbuf + par * 1024 + 0 * 256 + kh * 128);
            const ulonglong2* hp1 = (const ulonglong2*)(sm_hbuf + par * 1024 + 1 * 256 + kh * 128);
            const ulonglong2* hp2 = (const ulonglong2*)(sm_hbuf + par * 1024 + 2 * 256 + kh * 128);
            const ulonglong2* hp3 = (const ulonglong2*)(sm_hbuf + par * 1024 + 3 * 256 + kh * 128);
#pragma unroll
            for (int i = 0; i < 32; i++) {
                ulonglong2 h0 = hp0[i];
                fma2(aA0, wp[2 * i], h0.x); fma2(aB0, wp[2 * i + 1], h0.y);
                ulonglong2 h1 = hp1[i];
                fma2(aA1, wp[2 * i], h1.x); fma2(aB1, wp[2 * i + 1], h1.y);
                ulonglong2 h2 = hp2[i];
                fma2(aA2, wp[2 * i], h2.x); fma2(aB2, wp[2 * i + 1], h2.y);
                ulonglong2 h3 = hp3[i];
                fma2(aA3, wp[2 * i], h3.x); fma2(aB3, wp[2 * i + 1], h3.y);
            }
        }
        {
            F2 xa, xb;
            float s0, s1, s2, s3;
            xa.u = aA0; xb.u = aB0; s0 = (xa.f.x + xa.f.y) + (xb.f.x + xb.f.y);
            xa.u = aA1; xb.u = aB1; s1 = (xa.f.x + xa.f.y) + (xb.f.x + xb.f.y);
            xa.u = aA2; xb.u = aB2; s2 = (xa.f.x + xa.f.y) + (xb.f.x + xb.f.y);
            xa.u = aA3; xb.u = aB3; s3 = (xa.f.x + xa.f.y) + (xb.f.x + xb.f.y);
            ((float4*)sm_part)[kh * 128 + row] = make_float4(s0, s1, s2, s3);
        }
        __syncthreads();

        // ---- pointwise: unit u, col; gather 4 gates from both K-halves ----
        if (tid < 128) {
            const float* p0 = sm_part;          // kh=0
            const float* p1 = sm_part + 512;    // kh=1
            float gi = p0[(u)           * 4 + col] + p1[(u)           * 4 + col] + xg0 + b0;
            float gf = p0[(32 + u)      * 4 + col] + p1[(32 + u)      * 4 + col] + xg1 + b1;
            float gg = p0[(64 + u)      * 4 + col] + p1[(64 + u)      * 4 + col] + xg2 + b2;
            float go = p0[(96 + u)      * 4 + col] + p1[(96 + u)      * 4 + col] + xg3 + b3;
            creg = sigf(gf) * creg + sigf(gi) * tanhfast(gg);
            float h = sigf(go) * tanhfast(creg);
            uint32_t off = (uint32_t)((((par ^ 1) * 1024) + col * 256 + (int)r * 32 + u) * 4);
#pragma unroll
            for (int p8 = 0; p8 < 8; p8++)
                asm volatile("st.shared::cluster.f32 [%0], %1;"
                             :: "r"(peer[p8] + off), "f"(h) : "memory");
        }

        // stage next tokens + this step's noise while work drains
        if (tid >= 252) sm_tok[((t + 1) & 1) * 4 + (tid - 252)] = nxt_tok;
        if ((int)r < 4 && tid == 128) nz = noise[t * BATCH + colg0 + (int)r];

        asm volatile("barrier.cluster.arrive.aligned;" ::: "memory");
        asm volatile("barrier.cluster.wait.aligned;" ::: "memory");
    }

    // final pz for t_out = 2047 (h_2047 is in parity 0)
    if ((int)r < 4 && (tid >> 5) == 4) {
        int lane = tid & 31;
        float acc = 0.f;
        const float* hrow = sm_hbuf + (int)r * 256;   // parity 0
#pragma unroll
        for (int jj = 0; jj < 8; jj++)
            acc += hrow[lane + jj * 32] * sm_Wz[lane + jj * 32];
#pragma unroll
        for (int off = 16; off; off >>= 1)
            acc += __shfl_down_sync(0xffffffffu, acc, off);
        if (lane == 0) {
            float pz = sigf(acc + bz);
            int o = 2047 * BATCH + colg0 + (int)r;
            out[o]        = pz;
            out[TBsz + o] = (nz < pz) ? 1.f : 0.f;
        }
    }
}

// ---------------- kernel 3: per-column stable stream compaction ----------------
__global__ void __launch_bounds__(256)
compact_kernel(const int* __restrict__ sentences, float* __restrict__ out) {
    int b = blockIdx.x;
    int tid = threadIdx.x;
    __shared__ int wsum[8];
    __shared__ int s_total;

    int t0 = tid * 8;
    float zv[8];
    int pre[8];
    int cnt = 0;
#pragma unroll
    for (int i = 0; i < 8; i++) {
        zv[i]  = out[TBsz + (t0 + i) * BATCH + b];
        pre[i] = cnt;
        cnt += (zv[i] > 0.5f) ? 1 : 0;
    }
    int lane = tid & 31, w = tid >> 5;
    int x = cnt;
#pragma unroll
    for (int off = 1; off < 32; off <<= 1) {
        int y = __shfl_up_sync(0xffffffffu, x, off);
        if (lane >= off) x += y;
    }
    if (lane == 31) wsum[w] = x;
    __syncthreads();
    if (tid == 0) {
        int s = 0;
        for (int k = 0; k < 8; k++) { int v = wsum[k]; wsum[k] = s; s += v; }
        s_total = s;
    }
    __syncthreads();
    int base = wsum[w] + (x - cnt);
#pragma unroll
    for (int i = 0; i < 8; i++) {
        if (zv[i] > 0.5f) {
            int pos = base + pre[i];
            out[2 * TBsz + pos * BATCH + b] = (float)sentences[(t0 + i) * BATCH + b];
        }
    }
    int total = s_total;
    for (int p = total + tid; p < T_STEPS; p += 256)
        out[2 * TBsz + p * BATCH + b] = 0.0f;   // PAD_ID = 0
    if (tid == 0) out[3 * TBsz + b] = (float)total;
}

// ---------------- launch ----------------
extern "C" void kernel_launch(void* const* d_in, const int* in_sizes, int n_in,
                              void* d_out, int out_size) {
    const int*   sentences = (const int*)  d_in[0];
    const float* noise     = (const float*)d_in[1];
    const float* emb       = (const float*)d_in[2];
    const float* W_ih      = (const float*)d_in[3];
    const float* W_hh      = (const float*)d_in[4];
    const float* b_ih      = (const float*)d_in[5];
    const float* b_hh      = (const float*)d_in[6];
    const float* W_z       = (const float*)d_in[7];
    const float* b_z       = (const float*)d_in[8];
    float* out = (float*)d_out;

    cudaFuncSetAttribute(lstm_kernel, cudaFuncAttributeMaxDynamicSharedMemorySize,
                         LSTM_SMEM_BYTES);

    reorder_kernel<<<G4, 256>>>(W_hh, b_ih, b_hh);
    proj_kernel<<<dim3((VOCAB + BM - 1) / BM, G4 / BN), 256>>>(emb, W_ih);
    lstm_kernel<<<128, 256, LSTM_SMEM_BYTES>>>(sentences, noise, W_z, b_z, out);
    compact_kernel<<<BATCH, 256>>>(sentences, out);
}

// round 6
// speedup vs baseline: 2.1783x; 1.1230x over previous
#include <cuda_runtime.h>
#include <cuda_bf16.h>
#include <cstdint>
#include <math.h>

#define T_STEPS 2048
#define BATCH   64
#define EDIM    256
#define HDIM    256
#define G4      1024
#define VOCAB   50257
#define TBsz    (T_STEPS*BATCH)

typedef unsigned long long ull;

// ---------------- device scratch (no cudaMalloc allowed) ----------------
__device__ float d_P[(size_t)VOCAB * G4];   // projected embedding table, permuted cols

// permutation: j = g*256 + k, k = r*32+u  ->  pj = r*128 + g*32 + u
__device__ __forceinline__ int permj(int j) {
    int g = j >> 8; int k = j & 255; int r = k >> 5; int u = k & 31;
    return r * 128 + g * 32 + u;
}

__device__ __forceinline__ ull pack2(float a, float b) {
    ull r; asm("mov.b64 %0, {%1, %2};" : "=l"(r) : "f"(a), "f"(b)); return r;
}
__device__ __forceinline__ void fma2(ull& d, ull a, ull b) {
    asm("fma.rn.f32x2 %0, %1, %2, %0;" : "+l"(d) : "l"(a), "l"(b));
}
union F2 { ull u; float2 f; };

// ---------------- kernel 1: P = emb @ W_ih^T (NT gemm), permuted cols, f32x2 ----------------
#define BM 128
#define BN 128
#define BK 32
__global__ void __launch_bounds__(256)
proj_kernel(const float* __restrict__ emb, const float* __restrict__ Wih) {
    __shared__ float As[BK][BM + 1];
    __shared__ float Bs[BK][BN + 1];
    int l  = threadIdx.x;
    int v0 = blockIdx.x * BM;
    int j0 = blockIdx.y * BN;
    int ty = l >> 4, tx = l & 15;

    ull acc2[8][4];
#pragma unroll
    for (int i = 0; i < 8; i++)
#pragma unroll
        for (int j = 0; j < 4; j++) acc2[i][j] = 0ull;

    for (int kt = 0; kt < EDIM; kt += BK) {
        for (int idx = l; idx < BM * BK; idx += 256) {
            int vr = idx >> 5; int e = idx & 31;
            int v = v0 + vr;
            As[e][vr] = (v < VOCAB) ? emb[v * EDIM + kt + e] : 0.f;
        }
        for (int idx = l; idx < BN * BK; idx += 256) {
            int jr = idx >> 5; int e = idx & 31;
            Bs[e][jr] = Wih[(j0 + jr) * EDIM + kt + e];
        }
        __syncthreads();
#pragma unroll
        for (int kk = 0; kk < BK; kk++) {
            float a[8], b[8];
#pragma unroll
            for (int i = 0; i < 8; i++) a[i] = As[kk][ty * 8 + i];
#pragma unroll
            for (int i = 0; i < 8; i++) b[i] = Bs[kk][tx * 8 + i];
            ull pa[8], pb[4];
#pragma unroll
            for (int i = 0; i < 8; i++) pa[i] = pack2(a[i], a[i]);
#pragma unroll
            for (int j = 0; j < 4; j++) pb[j] = pack2(b[2 * j], b[2 * j + 1]);
#pragma unroll
            for (int i = 0; i < 8; i++)
#pragma unroll
                for (int j = 0; j < 4; j++) fma2(acc2[i][j], pa[i], pb[j]);
        }
        __syncthreads();
    }
    int jb  = j0 + tx * 8;
    int pj0 = permj(jb);
#pragma unroll
    for (int i = 0; i < 8; i++) {
        int v = v0 + ty * 8 + i;
        if (v < VOCAB) {
#pragma unroll
            for (int j = 0; j < 4; j++) {
                F2 x; x.u = acc2[i][j];
                d_P[(size_t)v * G4 + pj0 + 2 * j]     = x.f.x;
                d_P[(size_t)v * G4 + pj0 + 2 * j + 1] = x.f.y;
            }
        }
    }
}

// ---------------- kernel 2: persistent cluster LSTM + fused compaction ----------------
__device__ __forceinline__ void cluster_sync_() {
    asm volatile("barrier.cluster.arrive.aligned;" ::: "memory");
    asm volatile("barrier.cluster.wait.aligned;" ::: "memory");
}
__device__ __forceinline__ float sigf(float x) {
    return __fdividef(1.f, 1.f + __expf(-x));
}
__device__ __forceinline__ float tanhfast(float x) {
    return 1.f - 2.f * __fdividef(1.f, __expf(2.f * x) + 1.f);
}
__device__ __forceinline__ void mbar_wait_parity(uint32_t addr, uint32_t ph) {
    uint32_t done;
    asm volatile("{\n\t.reg .pred p;\n\t"
                 "mbarrier.try_wait.parity.acquire.cta.shared::cta.b64 p, [%1], %2;\n\t"
                 "selp.b32 %0, 1, 0, p;\n\t}"
                 : "=r"(done) : "r"(addr), "r"(ph) : "memory");
    if (!done) {
        asm volatile("{\n\t.reg .pred P1;\n\t"
                     "WL_%=:\n\t"
                     "mbarrier.try_wait.parity.acquire.cta.shared::cta.b64 P1, [%0], %1, 0x989680;\n\t"
                     "@P1 bra.uni WD_%=;\n\t"
                     "bra.uni WL_%=;\n\t"
                     "WD_%=:\n\t}"
                     :: "r"(addr), "r"(ph) : "memory");
    }
}

// smem float layout
#define SM_MB   0        // 4 floats = 2 x u64 mbarriers
#define SM_HB   4        // 2048 : 2 par x 4 col x 256 k
#define SM_PART 2052     // 1024 : 2 kh x 128 row x 4 col (float4 per row); also int scratch at end
#define SM_WZ   3076     // 256
#define SM_TOK  3332     // 8 ints (2 par x 4 col)
#define SM_ZB   3340     // 64 ints of z bits
#define SM_FLOATS 3408
#define LSTM_SMEM_BYTES (SM_FLOATS * 4)

__global__ void __launch_bounds__(256, 1) __cluster_dims__(8, 1, 1)
lstm_kernel(const int* __restrict__ sentences, const float* __restrict__ noise,
            const float* __restrict__ W_hh, const float* __restrict__ b_ih,
            const float* __restrict__ b_hh,
            const float* __restrict__ W_z, const float* __restrict__ b_z_p,
            float* __restrict__ out) {
    extern __shared__ float sm[];
    float* sm_hbuf  = sm + SM_HB;
    float* sm_part  = sm + SM_PART;
    float* sm_Wz    = sm + SM_WZ;
    int*   sm_tok   = (int*)(sm + SM_TOK);
    int*   sm_zbits = (int*)(sm + SM_ZB);

    int tid = threadIdx.x;
    uint32_t r;
    asm("mov.u32 %0, %%cluster_ctarank;" : "=r"(r));
    int cid   = blockIdx.x >> 3;
    int colg0 = cid * 4;
    int row = tid & 127;          // gate-row within CTA slice (g*32+uu)
    int kh  = tid >> 7;           // K-half
    int u   = tid & 31;
    int col = (tid >> 5) & 3;

    // register-resident weights, loaded directly with inverse permutation:
    // slice row (g*32+uu) of CTA r  <->  original row j = g*256 + r*32 + uu
    ull wp[64];
    {
        int g = row >> 5, uu = row & 31;
        int j = g * 256 + (int)r * 32 + uu;
        const float2* wsrc = (const float2*)(W_hh + j * 256 + kh * 128);
#pragma unroll
        for (int i = 0; i < 64; i++) {
            float2 w = wsrc[i];
            wp[i] = pack2(w.x, w.y);
        }
    }

    sm_Wz[tid] = W_z[tid & 255];
    for (int idx = tid; idx < 2048; idx += 256) sm_hbuf[idx] = 0.f;
    for (int idx = tid; idx < 64; idx += 256) sm_zbits[idx] = 0;
    if (tid < 4) sm_tok[tid] = sentences[colg0 + tid];

    // mbarriers: init + pre-arm both (1 arrival from tid0's expect, 4096 tx bytes)
    uint32_t mb_local = (uint32_t)__cvta_generic_to_shared(sm + SM_MB);
    if (tid == 0) {
        asm volatile("mbarrier.init.shared.b64 [%0], 1;" :: "r"(mb_local)     : "memory");
        asm volatile("mbarrier.init.shared.b64 [%0], 1;" :: "r"(mb_local + 8) : "memory");
        asm volatile("mbarrier.arrive.expect_tx.shared.b64 _, [%0], 4096;" :: "r"(mb_local)     : "memory");
        asm volatile("mbarrier.arrive.expect_tx.shared.b64 _, [%0], 4096;" :: "r"(mb_local + 8) : "memory");
    }

    // pointwise constants (tid<128 -> unit u, col)
    float b0 = 0.f, b1 = 0.f, b2 = 0.f, b3 = 0.f, creg = 0.f;
    if (tid < 128) {
        int jb0 = 0 * 256 + (int)r * 32 + u;
        b0 = b_ih[jb0]        + b_hh[jb0];
        b1 = b_ih[jb0 + 256]  + b_hh[jb0 + 256];
        b2 = b_ih[jb0 + 512]  + b_hh[jb0 + 512];
        b3 = b_ih[jb0 + 768]  + b_hh[jb0 + 768];
    }
    float bz = b_z_p[0];
    __syncthreads();

    // peer addresses for hbuf and mbarriers
    uint32_t hb_local = (uint32_t)__cvta_generic_to_shared(sm_hbuf);
    uint32_t peer_hb[8], peer_mb[8];
#pragma unroll
    for (int p = 0; p < 8; p++) {
        asm("mapa.shared::cluster.u32 %0, %1, %2;" : "=r"(peer_hb[p]) : "r"(hb_local), "r"(p));
        asm("mapa.shared::cluster.u32 %0, %1, %2;" : "=r"(peer_mb[p]) : "r"(mb_local), "r"(p));
    }

    float nz = 0.f;
    uint32_t ph0 = 0, ph1 = 0;      // phase parity for mbar[0], mbar[1]
    uint32_t zchunk = 0;
    cluster_sync_();                 // all barriers initialized cluster-wide

    for (int t = 0; t < T_STEPS; t++) {
        int par  = t & 1;
        int wpar = par ^ 1;

        // ---- x-gate loads for this step (pointwise threads), overlap matmul ----
        float xg0 = 0.f, xg1 = 0.f, xg2 = 0.f, xg3 = 0.f;
        if (tid < 128) {
            int tok = sm_tok[par * 4 + col];
            const float* Pp = d_P + (size_t)tok * G4 + (int)r * 128 + u;
            xg0 = Pp[0]; xg1 = Pp[32]; xg2 = Pp[64]; xg3 = Pp[96];
        }

        // ---- next-step token prefetch ----
        int nxt_tok = 0;
        if (tid >= 252) {
            int tn = (t + 1 < T_STEPS) ? t + 1 : T_STEPS - 1;
            nxt_tok = sentences[tn * BATCH + colg0 + (tid - 252)];
        }

        // ---- pz/z for output t-1: CTA r (<4) column colg0+r, warp 4 ----
        if ((int)r < 4 && (tid >> 5) == 4 && t > 0) {
            int lane = tid & 31;
            float acc = 0.f;
            const float* hrow = sm_hbuf + par * 1024 + (int)r * 256;
#pragma unroll
            for (int jj = 0; jj < 8; jj++)
                acc += hrow[lane + jj * 32] * sm_Wz[lane + jj * 32];
#pragma unroll
            for (int off = 16; off; off >>= 1)
                acc += __shfl_down_sync(0xffffffffu, acc, off);
            if (lane == 0) {
                float pz = sigf(acc + bz);
                int oi = t - 1;
                int o = oi * BATCH + colg0 + (int)r;
                uint32_t zb = (nz < pz) ? 1u : 0u;
                out[o]        = pz;
                out[TBsz + o] = (float)zb;
                zchunk |= zb << (oi & 31);
                if ((oi & 31) == 31) { sm_zbits[oi >> 5] = (int)zchunk; zchunk = 0; }
            }
        }

        // ---- recurrent matmul: row x 4 cols over K-half, weights in registers ----
        ull aA0 = 0ull, aB0 = 0ull, aA1 = 0ull, aB1 = 0ull;
        ull aA2 = 0ull, aB2 = 0ull, aA3 = 0ull, aB3 = 0ull;
        {
            const ulonglong2* hp0 = (const ulonglong2*)(sm_hbuf + par * 1024 + 0 * 256 + kh * 128);
            const ulonglong2* hp1 = (const ulonglong2*)(sm_hbuf + par * 1024 + 1 * 256 + kh * 128);
            const ulonglong2* hp2 = (const ulonglong2*)(sm_hbuf + par * 1024 + 2 * 256 + kh * 128);
            const ulonglong2* hp3 = (const ulonglong2*)(sm_hbuf + par * 1024 + 3 * 256 + kh * 128);
#pragma unroll
            for (int i = 0; i < 32; i++) {
                ulonglong2 h0 = hp0[i];
                fma2(aA0, wp[2 * i], h0.x); fma2(aB0, wp[2 * i + 1], h0.y);
                ulonglong2 h1 = hp1[i];
                fma2(aA1, wp[2 * i], h1.x); fma2(aB1, wp[2 * i + 1], h1.y);
                ulonglong2 h2 = hp2[i];
                fma2(aA2, wp[2 * i], h2.x); fma2(aB2, wp[2 * i + 1], h2.y);
                ulonglong2 h3 = hp3[i];
                fma2(aA3, wp[2 * i], h3.x); fma2(aB3, wp[2 * i + 1], h3.y);
            }
        }
        {
            F2 xa, xb;
            float s0, s1, s2, s3;
            xa.u = aA0; xb.u = aB0; s0 = (xa.f.x + xa.f.y) + (xb.f.x + xb.f.y);
            xa.u = aA1; xb.u = aB1; s1 = (xa.f.x + xa.f.y) + (xb.f.x + xb.f.y);
            xa.u = aA2; xb.u = aB2; s2 = (xa.f.x + xa.f.y) + (xb.f.x + xb.f.y);
            xa.u = aA3; xb.u = aB3; s3 = (xa.f.x + xa.f.y) + (xb.f.x + xb.f.y);
            ((float4*)sm_part)[kh * 128 + row] = make_float4(s0, s1, s2, s3);
        }
        __syncthreads();

        // ---- pointwise + h broadcast via st.async (tx-counted on peer mbarriers) ----
        if (tid < 128) {
            const float* p0 = sm_part;
            const float* p1 = sm_part + 512;
            float gi = p0[(u)      * 4 + col] + p1[(u)      * 4 + col] + xg0 + b0;
            float gf = p0[(32 + u) * 4 + col] + p1[(32 + u) * 4 + col] + xg1 + b1;
            float gg = p0[(64 + u) * 4 + col] + p1[(64 + u) * 4 + col] + xg2 + b2;
            float go = p0[(96 + u) * 4 + col] + p1[(96 + u) * 4 + col] + xg3 + b3;
            creg = sigf(gf) * creg + sigf(gi) * tanhfast(gg);
            float h = sigf(go) * tanhfast(creg);
            uint32_t off  = (uint32_t)(((wpar * 1024) + col * 256 + (int)r * 32 + u) * 4);
            uint32_t moff = (uint32_t)(wpar * 8);
#pragma unroll
            for (int p8 = 0; p8 < 8; p8++)
                asm volatile("st.async.shared::cluster.mbarrier::complete_tx::bytes.f32 [%0], %1, [%2];"
                             :: "r"(peer_hb[p8] + off), "f"(h), "r"(peer_mb[p8] + moff) : "memory");
        }

        // stage next tokens + this step's noise while stores fly
        if (tid >= 252) sm_tok[((t + 1) & 1) * 4 + (tid - 252)] = nxt_tok;
        if ((int)r < 4 && tid == 128) nz = noise[t * BATCH + colg0 + (int)r];

        // ---- wait for all 8 CTAs' h-slices (4096 tx bytes), then re-arm ----
        if (wpar == 0) { mbar_wait_parity(mb_local,     ph0); ph0 ^= 1; }
        else           { mbar_wait_parity(mb_local + 8, ph1); ph1 ^= 1; }
        if (tid == 0)
            asm volatile("mbarrier.arrive.expect_tx.shared.b64 _, [%0], 4096;"
                         :: "r"(mb_local + (uint32_t)(wpar * 8)) : "memory");
    }

    // final pz for t_out = 2047 (h_2047 is in parity 0)
    if ((int)r < 4 && (tid >> 5) == 4) {
        int lane = tid & 31;
        float acc = 0.f;
        const float* hrow = sm_hbuf + (int)r * 256;
#pragma unroll
        for (int jj = 0; jj < 8; jj++)
            acc += hrow[lane + jj * 32] * sm_Wz[lane + jj * 32];
#pragma unroll
        for (int off = 16; off; off >>= 1)
            acc += __shfl_down_sync(0xffffffffu, acc, off);
        if (lane == 0) {
            float pz = sigf(acc + bz);
            int o = 2047 * BATCH + colg0 + (int)r;
            uint32_t zb = (nz < pz) ? 1u : 0u;
            out[o]        = pz;
            out[TBsz + o] = (float)zb;
            zchunk |= zb << 31;
            sm_zbits[63] = (int)zchunk;
        }
    }
    __syncthreads();

    // ---- fused per-column compaction (CTA r<4 handles column colg0+r) ----
    {
        int b = colg0 + (int)r;
        int lane = tid & 31, w = tid >> 5;
        int* wsum = (int*)sm_part;          // scratch
        int* s_total = wsum + 8;

        uint32_t byte = ((uint32_t)sm_zbits[tid >> 2] >> ((tid & 3) * 8)) & 0xFFu;
        int cnt = __popc(byte);
        int x = cnt;
#pragma unroll
        for (int off = 1; off < 32; off <<= 1) {
            int y = __shfl_up_sync(0xffffffffu, x, off);
            if (lane >= off) x += y;
        }
        if (lane == 31) wsum[w] = x;
        __syncthreads();
        if (tid == 0) {
            int s = 0;
            for (int k = 0; k < 8; k++) { int v = wsum[k]; wsum[k] = s; s += v; }
            *s_total = s;
        }
        __syncthreads();
        if ((int)r < 4) {
            int base = wsum[w] + (x - cnt);
            int t0 = tid * 8;
            int pos = base;
#pragma unroll
            for (int k = 0; k < 8; k++) {
                if ((byte >> k) & 1u) {
                    out[2 * TBsz + pos * BATCH + b] = (float)sentences[(t0 + k) * BATCH + b];
                    pos++;
                }
            }
            int total = *s_total;
            for (int p = total + tid; p < T_STEPS; p += 256)
                out[2 * TBsz + p * BATCH + b] = 0.0f;   // PAD_ID = 0
            if (tid == 0) out[3 * TBsz + b] = (float)total;
        }
    }
}

// ---------------- launch ----------------
extern "C" void kernel_launch(void* const* d_in, const int* in_sizes, int n_in,
                              void* d_out, int out_size) {
    const int*   sentences = (const int*)  d_in[0];
    const float* noise     = (const float*)d_in[1];
    const float* emb       = (const float*)d_in[2];
    const float* W_ih      = (const float*)d_in[3];
    const float* W_hh      = (const float*)d_in[4];
    const float* b_ih      = (const float*)d_in[5];
    const float* b_hh      = (const float*)d_in[6];
    const float* W_z       = (const float*)d_in[7];
    const float* b_z       = (const float*)d_in[8];
    float* out = (float*)d_out;

    cudaFuncSetAttribute(lstm_kernel, cudaFuncAttributeMaxDynamicSharedMemorySize,
                         LSTM_SMEM_BYTES);

    proj_kernel<<<dim3((VOCAB + BM - 1) / BM, G4 / BN), 256>>>(emb, W_ih);
    lstm_kernel<<<128, 256, LSTM_SMEM_BYTES>>>(sentences, noise, W_hh, b_ih, b_hh,
                                               W_z, b_z, out);
}